// round 3
// baseline (speedup 1.0000x reference)
#include <cuda_runtime.h>
#include <stdint.h>

#define P_TOTAL 80000
#define OUTC    64
#define XL      432
#define YL      496

__device__ __forceinline__ uint64_t pack2(float x, float y) {
    uint64_t r; asm("mov.b64 %0, {%1,%2};" : "=l"(r) : "f"(x), "f"(y)); return r;
}
__device__ __forceinline__ uint64_t pack2s(float x) {
    uint64_t r; asm("mov.b64 %0, {%1,%1};" : "=l"(r) : "f"(x)); return r;
}
__device__ __forceinline__ uint64_t fma2(uint64_t a, uint64_t b, uint64_t c) {
    uint64_t d;
    asm("fma.rn.f32x2 %0, %1, %2, %3;" : "=l"(d) : "l"(a), "l"(b), "l"(c));
    return d;
}
__device__ __forceinline__ float2 unpack2(uint64_t v) {
    float2 f; asm("mov.b64 {%0,%1}, %2;" : "=f"(f.x), "=f"(f.y) : "l"(v)); return f;
}

// One warp per pillar, lane = point (N_PTS == 32).
// Each lane owns channel pair (lane, lane+32), packed as f32x2.
// Feature folding: with pillar-uniform mean (mx,my,mz) and center (cx,cy),
//   x_c = w0 f0 + w1 f1 + w2 f2 + w3 f3 + w4(f0-mx) + w5(f1-my) + w6(f2-mz)
//       + w7(f0-cx) + w8(f1-cy)
// BN fold: y_c = a_c x_c + b_c, a = gamma*rsqrt(var+eps), b = beta - mean*a.
//   y_c = f0*W0 + f1*W1 + f2*W2 + f3*W3 + pconst
//   W0=a(w0+w4+w7), W1=a(w1+w5+w8), W2=a(w2+w6), W3=a*w3
//   pconst = b - a*(w4 mx + w5 my + w6 mz + w7 cx + w8 cy)
// Masked (invalid) point => features all 0 => y = b. relu∘max = max then relu.
__global__ void __launch_bounds__(256) pillar_kernel(
    const float4* __restrict__ pillars,   // P*32 float4
    const int*    __restrict__ npoints,   // P
    const int4*   __restrict__ coors,     // P int4: (b, x, y, 0)
    const float*  __restrict__ conv_w,    // 64*9 row-major
    const float*  __restrict__ bn_gamma,
    const float*  __restrict__ bn_beta,
    const float*  __restrict__ bn_mean,
    const float*  __restrict__ bn_var,
    float*        __restrict__ out)       // 4*64*496*432, pre-zeroed
{
    const int lane   = threadIdx.x & 31;
    const int warp   = (blockIdx.x * blockDim.x + threadIdx.x) >> 5;
    const int nwarps = (gridDim.x * blockDim.x) >> 5;

    const int c0 = lane, c1 = lane + 32;
    const float a0 = bn_gamma[c0] * rsqrtf(bn_var[c0] + 1e-3f);
    const float a1 = bn_gamma[c1] * rsqrtf(bn_var[c1] + 1e-3f);
    const float b0 = bn_beta[c0] - bn_mean[c0] * a0;
    const float b1 = bn_beta[c1] - bn_mean[c1] * a1;
    const uint64_t b2 = pack2(b0, b1);

    float u[9], v[9];
#pragma unroll
    for (int k = 0; k < 9; k++) {
        u[k] = conv_w[c0 * 9 + k] * a0;
        v[k] = conv_w[c1 * 9 + k] * a1;
    }
    const uint64_t W0  = pack2(u[0] + u[4] + u[7], v[0] + v[4] + v[7]);
    const uint64_t W1  = pack2(u[1] + u[5] + u[8], v[1] + v[5] + v[8]);
    const uint64_t W2  = pack2(u[2] + u[6],        v[2] + v[6]);
    const uint64_t W3  = pack2(u[3],               v[3]);
    const uint64_t nW4 = pack2(-u[4], -v[4]);
    const uint64_t nW5 = pack2(-u[5], -v[5]);
    const uint64_t nW6 = pack2(-u[6], -v[6]);
    const uint64_t nW7 = pack2(-u[7], -v[7]);
    const uint64_t nW8 = pack2(-u[8], -v[8]);

    const float VXc = 0.16f, VYc = 0.16f;
    const float XOFF = 0.08f, YOFF = 0.08f - 39.68f;

    for (int p = warp; p < P_TOTAL; p += nwarps) {
        const float4 pt = pillars[p * 32 + lane];
        const int    np = npoints[p];
        const int4   cb = coors[p];

        // warp-wide sum over ALL 32 points (matches reference: sum all, /np)
        float sx = pt.x, sy = pt.y, sz = pt.z;
#pragma unroll
        for (int o = 16; o > 0; o >>= 1) {
            sx += __shfl_xor_sync(0xFFFFFFFFu, sx, o);
            sy += __shfl_xor_sync(0xFFFFFFFFu, sy, o);
            sz += __shfl_xor_sync(0xFFFFFFFFu, sz, o);
        }
        const float inv = __fdividef(1.0f, (float)np);
        const float mx = sx * inv, my = sy * inv, mz = sz * inv;
        const float cx = (float)cb.y * VXc + XOFF;
        const float cy = (float)cb.z * VYc + YOFF;

        uint64_t pc = b2;
        pc = fma2(pack2s(mx), nW4, pc);
        pc = fma2(pack2s(my), nW5, pc);
        pc = fma2(pack2s(mz), nW6, pc);
        pc = fma2(pack2s(cx), nW7, pc);
        pc = fma2(pack2s(cy), nW8, pc);

        float m0 = -3.402823466e38f, m1 = -3.402823466e38f;
        for (int q = 0; q < np; q++) {
            const float f0 = __shfl_sync(0xFFFFFFFFu, pt.x, q);
            const float f1 = __shfl_sync(0xFFFFFFFFu, pt.y, q);
            const float f2 = __shfl_sync(0xFFFFFFFFu, pt.z, q);
            const float f3 = __shfl_sync(0xFFFFFFFFu, pt.w, q);
            uint64_t d = pc;
            d = fma2(pack2s(f0), W0, d);
            d = fma2(pack2s(f1), W1, d);
            d = fma2(pack2s(f2), W2, d);
            d = fma2(pack2s(f3), W3, d);
            const float2 dv = unpack2(d);
            m0 = fmaxf(m0, dv.x);
            m1 = fmaxf(m1, dv.y);
        }
        if (np < 32) { m0 = fmaxf(m0, b0); m1 = fmaxf(m1, b1); }
        m0 = fmaxf(m0, 0.0f);
        m1 = fmaxf(m1, 0.0f);

        // out[b][c][y][x] with shape (4, 64, 496, 432)
        const int base = ((cb.x * OUTC) * YL + cb.z) * XL + cb.y;
        out[base + c0 * (YL * XL)] = m0;
        out[base + c1 * (YL * XL)] = m1;
    }
}

extern "C" void kernel_launch(void* const* d_in, const int* in_sizes, int n_in,
                              void* d_out, int out_size) {
    const float4* pillars  = (const float4*)d_in[0];
    const int*    npoints  = (const int*)d_in[1];
    const int4*   coors    = (const int4*)d_in[2];
    const float*  conv_w   = (const float*)d_in[3];
    const float*  bn_gamma = (const float*)d_in[4];
    const float*  bn_beta  = (const float*)d_in[5];
    const float*  bn_mean  = (const float*)d_in[6];
    const float*  bn_var   = (const float*)d_in[7];
    float* out = (float*)d_out;

    cudaMemsetAsync(out, 0, (size_t)out_size * sizeof(float));
    pillar_kernel<<<1024, 256>>>(pillars, npoints, coors, conv_w,
                                 bn_gamma, bn_beta, bn_mean, bn_var, out);
}

// round 6
// speedup vs baseline: 2.2869x; 2.2869x over previous
#include <cuda_runtime.h>
#include <stdint.h>
#include <float.h>

#define P_TOTAL 80000
#define OUTC    64
#define XL      432
#define YL      496
#define BS      4
#define PLANE   (YL * XL)           // 214272
#define WARPS_PER_BLK 8
#define GRID1   (P_TOTAL / WARPS_PER_BLK)   // 10000

// Scratch (device globals — no allocation allowed)
__device__ float g_pooled[P_TOTAL * OUTC];     // 20.5 MB, L2-resident
__device__ int   g_map[BS * YL * XL];          // 3.4 MB inverse map
__device__ float g_W[10][OUTC];                // folded weights: W0..W3, -W4..-W8, bias

// ---------------------------------------------------------------------------
// Fold conv weights + BN into 4 effective weights, 5 negated mean/center
// weights, and a bias, per channel.
//   y_c = f0*W0 + f1*W1 + f2*W2 + f3*W3 + (bb - W4*mx - W5*my - W6*mz - W7*cx - W8*cy)
// ---------------------------------------------------------------------------
__global__ void k_prep(const float* __restrict__ conv_w,
                       const float* __restrict__ gamma,
                       const float* __restrict__ beta,
                       const float* __restrict__ mean,
                       const float* __restrict__ var)
{
    int c = threadIdx.x;
    if (c >= OUTC) return;
    float a  = gamma[c] * rsqrtf(var[c] + 1e-3f);
    float bb = beta[c] - mean[c] * a;
    float u[9];
#pragma unroll
    for (int k = 0; k < 9; k++) u[k] = conv_w[c * 9 + k] * a;
    g_W[0][c] = u[0] + u[4] + u[7];
    g_W[1][c] = u[1] + u[5] + u[8];
    g_W[2][c] = u[2] + u[6];
    g_W[3][c] = u[3];
    g_W[4][c] = -u[4];
    g_W[5][c] = -u[5];
    g_W[6][c] = -u[6];
    g_W[7][c] = -u[7];
    g_W[8][c] = -u[8];
    g_W[9][c] = bb;
}

// ---------------------------------------------------------------------------
// k1: one warp per pillar.
//  Stage A (lane = point): coalesced float4 load -> smem; shfl-reduce x,y,z sums.
//  Stage B (lane = channel pair c, c+32): loop valid points via LDS.128
//  broadcast, 8 FFMA + 2 FMAX per point. Coalesced pooled write + map write.
// ---------------------------------------------------------------------------
__global__ void __launch_bounds__(256) k1(
    const float4* __restrict__ pillars,
    const int*    __restrict__ npoints,
    const int4*   __restrict__ coors)
{
    __shared__ float4 spts[WARPS_PER_BLK][32];
    __shared__ float  sW[10][OUTC];

    const int tid  = threadIdx.x;
    const int w    = tid >> 5;
    const int lane = tid & 31;
    const int p    = blockIdx.x * WARPS_PER_BLK + w;

    // cooperative weight-table load (640 floats)
    for (int i = tid; i < 10 * OUTC; i += 256)
        (&sW[0][0])[i] = (&g_W[0][0])[i];

    const float4 pt = pillars[p * 32 + lane];
    spts[w][lane] = pt;

    float sx = pt.x, sy = pt.y, sz = pt.z;
#pragma unroll
    for (int o = 16; o > 0; o >>= 1) {
        sx += __shfl_xor_sync(0xFFFFFFFFu, sx, o);
        sy += __shfl_xor_sync(0xFFFFFFFFu, sy, o);
        sz += __shfl_xor_sync(0xFFFFFFFFu, sz, o);
    }
    const int  np = npoints[p];
    const int4 cb = coors[p];

    __syncthreads();   // sW ready (also orders spts)

    const int c0 = lane, c1 = lane + 32;
    const float w0a = sW[0][c0], w1a = sW[1][c0], w2a = sW[2][c0], w3a = sW[3][c0];
    const float w0b = sW[0][c1], w1b = sW[1][c1], w2b = sW[2][c1], w3b = sW[3][c1];
    const float bba = sW[9][c0], bbb = sW[9][c1];

    const float inv = __fdividef(1.0f, (float)np);
    const float mx = sx * inv, my = sy * inv, mz = sz * inv;
    const float cx = (float)cb.y * 0.16f + 0.08f;
    const float cy = (float)cb.z * 0.16f + (0.08f - 39.68f);

    float pc0 = bba, pc1 = bbb;
    pc0 = fmaf(sW[4][c0], mx, pc0);  pc1 = fmaf(sW[4][c1], mx, pc1);
    pc0 = fmaf(sW[5][c0], my, pc0);  pc1 = fmaf(sW[5][c1], my, pc1);
    pc0 = fmaf(sW[6][c0], mz, pc0);  pc1 = fmaf(sW[6][c1], mz, pc1);
    pc0 = fmaf(sW[7][c0], cx, pc0);  pc1 = fmaf(sW[7][c1], cx, pc1);
    pc0 = fmaf(sW[8][c0], cy, pc0);  pc1 = fmaf(sW[8][c1], cy, pc1);

    float m0 = -FLT_MAX, m1 = -FLT_MAX;
    const float4* sp = spts[w];
    for (int q = 0; q < np; q++) {
        const float4 f = sp[q];                 // LDS.128 broadcast
        float d0 = pc0, d1 = pc1;
        d0 = fmaf(f.x, w0a, d0);  d1 = fmaf(f.x, w0b, d1);
        d0 = fmaf(f.y, w1a, d0);  d1 = fmaf(f.y, w1b, d1);
        d0 = fmaf(f.z, w2a, d0);  d1 = fmaf(f.z, w2b, d1);
        d0 = fmaf(f.w, w3a, d0);  d1 = fmaf(f.w, w3b, d1);
        m0 = fmaxf(m0, d0);
        m1 = fmaxf(m1, d1);
    }
    if (np < 32) { m0 = fmaxf(m0, bba); m1 = fmaxf(m1, bbb); }  // masked points => bias
    m0 = fmaxf(m0, 0.0f);
    m1 = fmaxf(m1, 0.0f);

    g_pooled[p * OUTC + c0] = m0;              // coalesced
    g_pooled[p * OUTC + c1] = m1;

    if (lane == 0)
        g_map[(cb.x * YL + cb.z) * XL + cb.y] = p;   // map[b][y][x] = pillar id
}

// ---------------------------------------------------------------------------
// k2: one block per (b, y) output row. Gather from L2-resident pooled with
// LDG.128 (4 channels/fetch), write 4 coalesced channel-plane rows with
// streaming stores. Empty cells write zeros (replaces the 219 MB memset).
// ---------------------------------------------------------------------------
__global__ void __launch_bounds__(256) k2(float* __restrict__ out)
{
    __shared__ int sidx[XL];
    const int b = blockIdx.x / YL;
    const int y = blockIdx.x % YL;
    const int tid = threadIdx.x;

    const int* mrow = g_map + (b * YL + y) * XL;
    for (int i = tid; i < XL; i += 256) sidx[i] = mrow[i];
    __syncthreads();

    for (int x = tid; x < XL; x += 256) {
        const int pid = sidx[x];
        const float4* src = (const float4*)(g_pooled + (pid < 0 ? 0 : pid) * OUTC);
        float* op = out + ((size_t)b * OUTC * YL + y) * XL + x;   // c=0 plane
#pragma unroll
        for (int cg = 0; cg < 16; cg++) {
            float4 v = make_float4(0.f, 0.f, 0.f, 0.f);
            if (pid >= 0) v = __ldg(src + cg);                    // 16B, 1 sector
            __stcs(op + (size_t)(4 * cg + 0) * PLANE, v.x);       // coalesced rows
            __stcs(op + (size_t)(4 * cg + 1) * PLANE, v.y);
            __stcs(op + (size_t)(4 * cg + 2) * PLANE, v.z);
            __stcs(op + (size_t)(4 * cg + 3) * PLANE, v.w);
        }
    }
}

extern "C" void kernel_launch(void* const* d_in, const int* in_sizes, int n_in,
                              void* d_out, int out_size) {
    const float4* pillars  = (const float4*)d_in[0];
    const int*    npoints  = (const int*)d_in[1];
    const int4*   coors    = (const int4*)d_in[2];
    const float*  conv_w   = (const float*)d_in[3];
    const float*  bn_gamma = (const float*)d_in[4];
    const float*  bn_beta  = (const float*)d_in[5];
    const float*  bn_mean  = (const float*)d_in[6];
    const float*  bn_var   = (const float*)d_in[7];
    float* out = (float*)d_out;

    void* map_ptr = nullptr;
    cudaGetSymbolAddress(&map_ptr, g_map);
    cudaMemsetAsync(map_ptr, 0xFF, sizeof(int) * BS * YL * XL);   // map = -1

    k_prep<<<1, 64>>>(conv_w, bn_gamma, bn_beta, bn_mean, bn_var);
    k1<<<GRID1, 256>>>(pillars, npoints, coors);
    k2<<<BS * YL, 256>>>(out);
}

// round 7
// speedup vs baseline: 2.4846x; 1.0865x over previous
#include <cuda_runtime.h>
#include <stdint.h>
#include <float.h>

#define P_TOTAL 80000
#define OUTC    64
#define XL      432
#define YL      496
#define BS      4
#define PLANE   (YL * XL)            // 214272
#define K1_BLOCKS 1184               // ~8 blocks/SM, grid-stride over pillars
#define K1_WARPS  (K1_BLOCKS * 8)

// Scratch (device globals — no allocation allowed)
__device__ float g_pooled[P_TOTAL * OUTC];   // 20.5 MB, L2-resident
__device__ int   g_map[BS * YL * XL];        // inverse map, memset to -1

__device__ __forceinline__ uint64_t pack2s(float x) {
    uint64_t r; asm("mov.b64 %0, {%1,%1};" : "=l"(r) : "f"(x)); return r;
}
__device__ __forceinline__ uint64_t fma2(uint64_t a, uint64_t b, uint64_t c) {
    uint64_t d;
    asm("fma.rn.f32x2 %0, %1, %2, %3;" : "=l"(d) : "l"(a), "l"(b), "l"(c));
    return d;
}
__device__ __forceinline__ float2 unpack2(uint64_t v) {
    float2 f; asm("mov.b64 {%0,%1}, %2;" : "=f"(f.x), "=f"(f.y) : "l"(v)); return f;
}

// ---------------------------------------------------------------------------
// k1: persistent-ish, one warp per pillar per iteration.
// Weight fold (BN+conv -> 4 eff. weights + 5 neg terms + bias) computed once
// per block in smem. Inner loop processes TWO points per step with packed
// fma.rn.f32x2: points staged SoA in smem so LDS.64 at a uniform address
// yields (f_q, f_{q+1}) directly. Halves fma-pipe pressure vs scalar FFMA.
// ---------------------------------------------------------------------------
__global__ void __launch_bounds__(256) k1(
    const float4* __restrict__ pillars,
    const int*    __restrict__ npoints,
    const int4*   __restrict__ coors,
    const float*  __restrict__ conv_w,
    const float*  __restrict__ gamma,
    const float*  __restrict__ beta,
    const float*  __restrict__ mean,
    const float*  __restrict__ var)
{
    __shared__ float sW[10][OUTC];
    __shared__ float sf[8][4][32];   // [warp][feature][point]

    const int tid  = threadIdx.x;
    const int w    = tid >> 5;
    const int lane = tid & 31;

    if (tid < OUTC) {
        const int c = tid;
        const float a  = gamma[c] * rsqrtf(var[c] + 1e-3f);
        const float bb = beta[c] - mean[c] * a;
        float u[9];
#pragma unroll
        for (int k = 0; k < 9; k++) u[k] = conv_w[c * 9 + k] * a;
        sW[0][c] = u[0] + u[4] + u[7];
        sW[1][c] = u[1] + u[5] + u[8];
        sW[2][c] = u[2] + u[6];
        sW[3][c] = u[3];
        sW[4][c] = -u[4];
        sW[5][c] = -u[5];
        sW[6][c] = -u[6];
        sW[7][c] = -u[7];
        sW[8][c] = -u[8];
        sW[9][c] = bb;
    }
    __syncthreads();

    const int c0 = lane, c1 = lane + 32;
    // duplicated packed weights for the 2-point f32x2 path
    const uint64_t W0a = pack2s(sW[0][c0]), W1a = pack2s(sW[1][c0]);
    const uint64_t W2a = pack2s(sW[2][c0]), W3a = pack2s(sW[3][c0]);
    const uint64_t W0b = pack2s(sW[0][c1]), W1b = pack2s(sW[1][c1]);
    const uint64_t W2b = pack2s(sW[2][c1]), W3b = pack2s(sW[3][c1]);
    const float n4a = sW[4][c0], n5a = sW[5][c0], n6a = sW[6][c0];
    const float n7a = sW[7][c0], n8a = sW[8][c0], bba = sW[9][c0];
    const float n4b = sW[4][c1], n5b = sW[5][c1], n6b = sW[6][c1];
    const float n7b = sW[7][c1], n8b = sW[8][c1], bbb = sW[9][c1];

    const int gw = (blockIdx.x * 256 + tid) >> 5;
    float* const sf0 = sf[w][0];
    float* const sf1 = sf[w][1];
    float* const sf2 = sf[w][2];
    float* const sf3 = sf[w][3];

    for (int p = gw; p < P_TOTAL; p += K1_WARPS) {
        const float4 pt = pillars[p * 32 + lane];
        const int    np = npoints[p];
        const int4   cb = coors[p];

        float sx = pt.x, sy = pt.y, sz = pt.z;
#pragma unroll
        for (int o = 16; o > 0; o >>= 1) {
            sx += __shfl_xor_sync(0xFFFFFFFFu, sx, o);
            sy += __shfl_xor_sync(0xFFFFFFFFu, sy, o);
            sz += __shfl_xor_sync(0xFFFFFFFFu, sz, o);
        }

        __syncwarp();                 // prior iteration's readers done
        sf0[lane] = pt.x;
        sf1[lane] = pt.y;
        sf2[lane] = pt.z;
        sf3[lane] = pt.w;
        __syncwarp();                 // staging visible

        const float inv = __fdividef(1.0f, (float)np);
        const float mx = sx * inv, my = sy * inv, mz = sz * inv;
        const float cx = (float)cb.y * 0.16f + 0.08f;
        const float cy = (float)cb.z * 0.16f + (0.08f - 39.68f);

        float pc0 = bba, pc1 = bbb;
        pc0 = fmaf(n4a, mx, pc0);  pc1 = fmaf(n4b, mx, pc1);
        pc0 = fmaf(n5a, my, pc0);  pc1 = fmaf(n5b, my, pc1);
        pc0 = fmaf(n6a, mz, pc0);  pc1 = fmaf(n6b, mz, pc1);
        pc0 = fmaf(n7a, cx, pc0);  pc1 = fmaf(n7b, cx, pc1);
        pc0 = fmaf(n8a, cy, pc0);  pc1 = fmaf(n8b, cy, pc1);
        const uint64_t pcA = pack2s(pc0);
        const uint64_t pcB = pack2s(pc1);

        float m0 = -FLT_MAX, m1 = -FLT_MAX;
        const int npair = np >> 1;
        for (int q = 0; q < npair; q++) {
            // uniform-address LDS.64 -> broadcast packed (f_q, f_{q+1})
            const uint64_t f0 = *(const uint64_t*)(sf0 + 2 * q);
            const uint64_t f1 = *(const uint64_t*)(sf1 + 2 * q);
            const uint64_t f2 = *(const uint64_t*)(sf2 + 2 * q);
            const uint64_t f3 = *(const uint64_t*)(sf3 + 2 * q);
            uint64_t dA = pcA, dB = pcB;
            dA = fma2(f0, W0a, dA);  dB = fma2(f0, W0b, dB);
            dA = fma2(f1, W1a, dA);  dB = fma2(f1, W1b, dB);
            dA = fma2(f2, W2a, dA);  dB = fma2(f2, W2b, dB);
            dA = fma2(f3, W3a, dA);  dB = fma2(f3, W3b, dB);
            const float2 va = unpack2(dA);
            const float2 vb = unpack2(dB);
            m0 = fmaxf(m0, fmaxf(va.x, va.y));
            m1 = fmaxf(m1, fmaxf(vb.x, vb.y));
        }
        if (np & 1) {                 // scalar tail for odd np
            const int q = np - 1;
            const float f0 = sf0[q], f1 = sf1[q], f2 = sf2[q], f3 = sf3[q];
            float d0 = pc0, d1 = pc1;
            d0 = fmaf(f0, sW[0][c0], d0);  d1 = fmaf(f0, sW[0][c1], d1);
            d0 = fmaf(f1, sW[1][c0], d0);  d1 = fmaf(f1, sW[1][c1], d1);
            d0 = fmaf(f2, sW[2][c0], d0);  d1 = fmaf(f2, sW[2][c1], d1);
            d0 = fmaf(f3, sW[3][c0], d0);  d1 = fmaf(f3, sW[3][c1], d1);
            m0 = fmaxf(m0, d0);
            m1 = fmaxf(m1, d1);
        }
        if (np < 32) { m0 = fmaxf(m0, bba); m1 = fmaxf(m1, bbb); }  // masked pts => bias
        m0 = fmaxf(m0, 0.0f);
        m1 = fmaxf(m1, 0.0f);

        g_pooled[p * OUTC + c0] = m0;                 // coalesced
        g_pooled[p * OUTC + c1] = m1;
        if (lane == 0)
            g_map[(cb.x * YL + cb.z) * XL + cb.y] = p;
    }
}

// ---------------------------------------------------------------------------
// k2: one block per (b, y) output row. Gather from L2-resident pooled with
// LDG.128 (4 channels/fetch), write coalesced channel-plane rows with
// streaming stores. Empty cells write zeros (replaces a 219 MB memset).
// ---------------------------------------------------------------------------
__global__ void __launch_bounds__(256) k2(float* __restrict__ out)
{
    __shared__ int sidx[XL];
    const int b = blockIdx.x / YL;
    const int y = blockIdx.x % YL;
    const int tid = threadIdx.x;

    const int* mrow = g_map + (b * YL + y) * XL;
    for (int i = tid; i < XL; i += 256) sidx[i] = mrow[i];
    __syncthreads();

    for (int x = tid; x < XL; x += 256) {
        const int pid = sidx[x];
        const float4* src = (const float4*)(g_pooled + (pid < 0 ? 0 : pid) * OUTC);
        float* op = out + ((size_t)b * OUTC * YL + y) * XL + x;   // c=0 plane
#pragma unroll
        for (int cg = 0; cg < 16; cg++) {
            float4 v = make_float4(0.f, 0.f, 0.f, 0.f);
            if (pid >= 0) v = __ldg(src + cg);                    // 16B, 1 sector
            __stcs(op + (size_t)(4 * cg + 0) * PLANE, v.x);       // coalesced rows
            __stcs(op + (size_t)(4 * cg + 1) * PLANE, v.y);
            __stcs(op + (size_t)(4 * cg + 2) * PLANE, v.z);
            __stcs(op + (size_t)(4 * cg + 3) * PLANE, v.w);
        }
    }
}

extern "C" void kernel_launch(void* const* d_in, const int* in_sizes, int n_in,
                              void* d_out, int out_size) {
    const float4* pillars  = (const float4*)d_in[0];
    const int*    npoints  = (const int*)d_in[1];
    const int4*   coors    = (const int4*)d_in[2];
    const float*  conv_w   = (const float*)d_in[3];
    const float*  bn_gamma = (const float*)d_in[4];
    const float*  bn_beta  = (const float*)d_in[5];
    const float*  bn_mean  = (const float*)d_in[6];
    const float*  bn_var   = (const float*)d_in[7];
    float* out = (float*)d_out;

    void* map_ptr = nullptr;
    cudaGetSymbolAddress(&map_ptr, g_map);
    cudaMemsetAsync(map_ptr, 0xFF, sizeof(int) * BS * YL * XL);   // map = -1

    k1<<<K1_BLOCKS, 256>>>(pillars, npoints, coors, conv_w,
                           bn_gamma, bn_beta, bn_mean, bn_var);
    k2<<<BS * YL, 256>>>(out);
}

// round 8
// speedup vs baseline: 2.5624x; 1.0313x over previous
#include <cuda_runtime.h>
#include <stdint.h>
#include <float.h>

#define P_TOTAL 80000
#define OUTC    64
#define XL      432
#define YL      496
#define BS      4
#define PLANE   (YL * XL)            // 214272
#define K1_BLOCKS 1184               // ~8 blocks/SM, grid-stride over pillars
#define K1_WARPS  (K1_BLOCKS * 8)

// Scratch (device globals — no allocation allowed)
__device__ float g_pooled[P_TOTAL * OUTC];   // 20.5 MB, mostly L2-resident
__device__ int   g_map[BS * YL * XL];        // inverse map, memset to -1

__device__ __forceinline__ uint64_t pack2s(float x) {
    uint64_t r; asm("mov.b64 %0, {%1,%1};" : "=l"(r) : "f"(x)); return r;
}
__device__ __forceinline__ uint64_t fma2(uint64_t a, uint64_t b, uint64_t c) {
    uint64_t d;
    asm("fma.rn.f32x2 %0, %1, %2, %3;" : "=l"(d) : "l"(a), "l"(b), "l"(c));
    return d;
}
__device__ __forceinline__ float2 unpack2(uint64_t v) {
    float2 f; asm("mov.b64 {%0,%1}, %2;" : "=f"(f.x), "=f"(f.y) : "l"(v)); return f;
}

// ---------------------------------------------------------------------------
// k1: grid-stride, one warp per pillar per iteration.
// BN+conv weights folded once per block into smem. Inner loop processes TWO
// points per step with packed fma.rn.f32x2; points staged SoA in smem so a
// uniform-address LDS.64 broadcasts (f_q, f_{q+1}) packed.
// ---------------------------------------------------------------------------
__global__ void __launch_bounds__(256) k1(
    const float4* __restrict__ pillars,
    const int*    __restrict__ npoints,
    const int4*   __restrict__ coors,
    const float*  __restrict__ conv_w,
    const float*  __restrict__ gamma,
    const float*  __restrict__ beta,
    const float*  __restrict__ mean,
    const float*  __restrict__ var)
{
    __shared__ float sW[10][OUTC];
    __shared__ float sf[8][4][32];   // [warp][feature][point]

    const int tid  = threadIdx.x;
    const int w    = tid >> 5;
    const int lane = tid & 31;

    if (tid < OUTC) {
        const int c = tid;
        const float a  = gamma[c] * rsqrtf(var[c] + 1e-3f);
        const float bb = beta[c] - mean[c] * a;
        float u[9];
#pragma unroll
        for (int k = 0; k < 9; k++) u[k] = conv_w[c * 9 + k] * a;
        sW[0][c] = u[0] + u[4] + u[7];
        sW[1][c] = u[1] + u[5] + u[8];
        sW[2][c] = u[2] + u[6];
        sW[3][c] = u[3];
        sW[4][c] = -u[4];
        sW[5][c] = -u[5];
        sW[6][c] = -u[6];
        sW[7][c] = -u[7];
        sW[8][c] = -u[8];
        sW[9][c] = bb;
    }
    __syncthreads();

    const int c0 = lane, c1 = lane + 32;
    const uint64_t W0a = pack2s(sW[0][c0]), W1a = pack2s(sW[1][c0]);
    const uint64_t W2a = pack2s(sW[2][c0]), W3a = pack2s(sW[3][c0]);
    const uint64_t W0b = pack2s(sW[0][c1]), W1b = pack2s(sW[1][c1]);
    const uint64_t W2b = pack2s(sW[2][c1]), W3b = pack2s(sW[3][c1]);
    const float n4a = sW[4][c0], n5a = sW[5][c0], n6a = sW[6][c0];
    const float n7a = sW[7][c0], n8a = sW[8][c0], bba = sW[9][c0];
    const float n4b = sW[4][c1], n5b = sW[5][c1], n6b = sW[6][c1];
    const float n7b = sW[7][c1], n8b = sW[8][c1], bbb = sW[9][c1];

    const int gw = (blockIdx.x * 256 + tid) >> 5;
    float* const sf0 = sf[w][0];
    float* const sf1 = sf[w][1];
    float* const sf2 = sf[w][2];
    float* const sf3 = sf[w][3];

    for (int p = gw; p < P_TOTAL; p += K1_WARPS) {
        const float4 pt = pillars[p * 32 + lane];
        const int    np = npoints[p];
        const int4   cb = coors[p];

        float sx = pt.x, sy = pt.y, sz = pt.z;
#pragma unroll
        for (int o = 16; o > 0; o >>= 1) {
            sx += __shfl_xor_sync(0xFFFFFFFFu, sx, o);
            sy += __shfl_xor_sync(0xFFFFFFFFu, sy, o);
            sz += __shfl_xor_sync(0xFFFFFFFFu, sz, o);
        }

        __syncwarp();                 // prior iteration's readers done
        sf0[lane] = pt.x;
        sf1[lane] = pt.y;
        sf2[lane] = pt.z;
        sf3[lane] = pt.w;
        __syncwarp();                 // staging visible

        const float inv = __fdividef(1.0f, (float)np);
        const float mx = sx * inv, my = sy * inv, mz = sz * inv;
        const float cx = (float)cb.y * 0.16f + 0.08f;
        const float cy = (float)cb.z * 0.16f + (0.08f - 39.68f);

        float pc0 = bba, pc1 = bbb;
        pc0 = fmaf(n4a, mx, pc0);  pc1 = fmaf(n4b, mx, pc1);
        pc0 = fmaf(n5a, my, pc0);  pc1 = fmaf(n5b, my, pc1);
        pc0 = fmaf(n6a, mz, pc0);  pc1 = fmaf(n6b, mz, pc1);
        pc0 = fmaf(n7a, cx, pc0);  pc1 = fmaf(n7b, cx, pc1);
        pc0 = fmaf(n8a, cy, pc0);  pc1 = fmaf(n8b, cy, pc1);
        const uint64_t pcA = pack2s(pc0);
        const uint64_t pcB = pack2s(pc1);

        float m0 = -FLT_MAX, m1 = -FLT_MAX;
        const int npair = np >> 1;
#pragma unroll 2
        for (int q = 0; q < npair; q++) {
            const uint64_t f0 = *(const uint64_t*)(sf0 + 2 * q);
            const uint64_t f1 = *(const uint64_t*)(sf1 + 2 * q);
            const uint64_t f2 = *(const uint64_t*)(sf2 + 2 * q);
            const uint64_t f3 = *(const uint64_t*)(sf3 + 2 * q);
            uint64_t dA = pcA, dB = pcB;
            dA = fma2(f0, W0a, dA);  dB = fma2(f0, W0b, dB);
            dA = fma2(f1, W1a, dA);  dB = fma2(f1, W1b, dB);
            dA = fma2(f2, W2a, dA);  dB = fma2(f2, W2b, dB);
            dA = fma2(f3, W3a, dA);  dB = fma2(f3, W3b, dB);
            const float2 va = unpack2(dA);
            const float2 vb = unpack2(dB);
            m0 = fmaxf(m0, fmaxf(va.x, va.y));
            m1 = fmaxf(m1, fmaxf(vb.x, vb.y));
        }
        if (np & 1) {                 // scalar tail for odd np
            const int q = np - 1;
            const float f0 = sf0[q], f1 = sf1[q], f2 = sf2[q], f3 = sf3[q];
            float d0 = pc0, d1 = pc1;
            d0 = fmaf(f0, sW[0][c0], d0);  d1 = fmaf(f0, sW[0][c1], d1);
            d0 = fmaf(f1, sW[1][c0], d0);  d1 = fmaf(f1, sW[1][c1], d1);
            d0 = fmaf(f2, sW[2][c0], d0);  d1 = fmaf(f2, sW[2][c1], d1);
            d0 = fmaf(f3, sW[3][c0], d0);  d1 = fmaf(f3, sW[3][c1], d1);
            m0 = fmaxf(m0, d0);
            m1 = fmaxf(m1, d1);
        }
        if (np < 32) { m0 = fmaxf(m0, bba); m1 = fmaxf(m1, bbb); }  // masked pts => bias
        m0 = fmaxf(m0, 0.0f);
        m1 = fmaxf(m1, 0.0f);

        g_pooled[p * OUTC + c0] = m0;                 // coalesced
        g_pooled[p * OUTC + c1] = m1;
        if (lane == 0)
            g_map[(cb.x * YL + cb.z) * XL + cb.y] = p;
    }
}

// ---------------------------------------------------------------------------
// k2: block = 4 output rows (blockDim 108x4); each thread owns 4 consecutive
// x cells. Reads its 4 pillar ids as one int4 (g_map rows are 16B-aligned:
// 432*4B = 1728B), gathers 4 channels from each of the 4 pillars (LDG.128
// from L2-resident g_pooled), transposes in registers, and writes one
// STG.128 per channel row (fully coalesced, streaming). Empty cells emit
// zeros — no big memset needed.
// ---------------------------------------------------------------------------
__global__ void __launch_bounds__(448) k2(float* __restrict__ out)
{
    const int chunk = threadIdx.x;              // 0..107
    const int row   = blockIdx.x * 4 + threadIdx.y;   // 0..1983
    const int b = row / YL;
    const int y = row - b * YL;

    const int4 pid = *(const int4*)(g_map + row * XL + chunk * 4);

    const float4* s0 = (const float4*)(g_pooled + (pid.x < 0 ? 0 : pid.x) * OUTC);
    const float4* s1 = (const float4*)(g_pooled + (pid.y < 0 ? 0 : pid.y) * OUTC);
    const float4* s2 = (const float4*)(g_pooled + (pid.z < 0 ? 0 : pid.z) * OUTC);
    const float4* s3 = (const float4*)(g_pooled + (pid.w < 0 ? 0 : pid.w) * OUTC);

    float* op = out + ((size_t)b * OUTC * YL + y) * XL + chunk * 4;  // c=0 plane

    const float4 z4 = make_float4(0.f, 0.f, 0.f, 0.f);
#pragma unroll
    for (int cg = 0; cg < 16; cg++) {
        const float4 v0 = (pid.x >= 0) ? __ldg(s0 + cg) : z4;
        const float4 v1 = (pid.y >= 0) ? __ldg(s1 + cg) : z4;
        const float4 v2 = (pid.z >= 0) ? __ldg(s2 + cg) : z4;
        const float4 v3 = (pid.w >= 0) ? __ldg(s3 + cg) : z4;
        __stcs((float4*)(op + (size_t)(4 * cg + 0) * PLANE),
               make_float4(v0.x, v1.x, v2.x, v3.x));
        __stcs((float4*)(op + (size_t)(4 * cg + 1) * PLANE),
               make_float4(v0.y, v1.y, v2.y, v3.y));
        __stcs((float4*)(op + (size_t)(4 * cg + 2) * PLANE),
               make_float4(v0.z, v1.z, v2.z, v3.z));
        __stcs((float4*)(op + (size_t)(4 * cg + 3) * PLANE),
               make_float4(v0.w, v1.w, v2.w, v3.w));
    }
}

extern "C" void kernel_launch(void* const* d_in, const int* in_sizes, int n_in,
                              void* d_out, int out_size) {
    const float4* pillars  = (const float4*)d_in[0];
    const int*    npoints  = (const int*)d_in[1];
    const int4*   coors    = (const int4*)d_in[2];
    const float*  conv_w   = (const float*)d_in[3];
    const float*  bn_gamma = (const float*)d_in[4];
    const float*  bn_beta  = (const float*)d_in[5];
    const float*  bn_mean  = (const float*)d_in[6];
    const float*  bn_var   = (const float*)d_in[7];
    float* out = (float*)d_out;

    void* map_ptr = nullptr;
    cudaGetSymbolAddress(&map_ptr, g_map);
    cudaMemsetAsync(map_ptr, 0xFF, sizeof(int) * BS * YL * XL);   // map = -1

    k1<<<K1_BLOCKS, 256>>>(pillars, npoints, coors, conv_w,
                           bn_gamma, bn_beta, bn_mean, bn_var);
    dim3 blk2(108, 4);
    k2<<<(BS * YL) / 4, blk2>>>(out);
}